// round 5
// baseline (speedup 1.0000x reference)
#include <cuda_runtime.h>
#include <math.h>

#define Bz 4
#define Sq 1024
#define Dm 1024
#define Hh 16
#define HDim 64
#define FFd 4096
#define NT (Bz*Sq)     // 4096 tokens
#define NH (Bz*Hh)     // 64 (b,h) pairs
#define EPSL 1e-5f
#define SCALE_INV 0.125f   // 1/sqrt(64)

// ------------------------- scratch (device globals; no mallocs allowed) ----
__device__ float g_xn  [NT*Dm];
__device__ float g_Q   [NT*Dm];
__device__ float g_K   [NT*Dm];
__device__ float g_V   [NT*Dm];
__device__ float g_QC  [NH*Sq*128];
__device__ float g_KC  [NH*Sq*128];
__device__ float g_sc  [67108864];      // [NH, Sq, Sq] = 256 MB
__device__ float g_attn[NT*Dm];
__device__ float g_x2  [NT*Dm];
__device__ float g_h0  [NT*Dm];
__device__ float g_th0 [NT*Dm];
__device__ float g_ht  [NT*FFd];
__device__ float g_spJ [NT*FFd];
__device__ float g_h1  [NT*FFd];
__device__ float g_th1 [NT*FFd];
__device__ float g_ht2 [NT*Dm];
__device__ float g_spJ2[NT*Dm];

// ------------------------- helpers ----------------------------------------
__device__ __forceinline__ float warp_sum(float v) {
#pragma unroll
    for (int o = 16; o > 0; o >>= 1) v += __shfl_xor_sync(0xffffffffu, v, o);
    return v;
}
__device__ __forceinline__ float warp_max(float v) {
#pragma unroll
    for (int o = 16; o > 0; o >>= 1) v = fmaxf(v, __shfl_xor_sync(0xffffffffu, v, o));
    return v;
}
__device__ __forceinline__ float gelu_exact(float x) {
    return 0.5f * x * (1.0f + erff(x * 0.70710678118654752f));
}

// ------------------------- layernorm over 1024 cols (+optional tanh copy) --
__global__ void __launch_bounds__(256) ln1024_kernel(
    const float* __restrict__ x, const float* __restrict__ g,
    const float* __restrict__ b, float* __restrict__ out, float* __restrict__ tout)
{
    __shared__ float sh[64];
    __shared__ float stats[2];
    const size_t base = (size_t)blockIdx.x * 1024;
    float vals[4];
    float s = 0.f, s2 = 0.f;
#pragma unroll
    for (int i = 0; i < 4; i++) {
        float v = x[base + threadIdx.x + i*256];
        vals[i] = v; s += v; s2 += v*v;
    }
    s = warp_sum(s); s2 = warp_sum(s2);
    int lane = threadIdx.x & 31, w = threadIdx.x >> 5;
    if (!lane) { sh[w] = s; sh[32+w] = s2; }
    __syncthreads();
    if (w == 0) {
        float a = (lane < 8) ? sh[lane] : 0.f;
        float c = (lane < 8) ? sh[32+lane] : 0.f;
        a = warp_sum(a); c = warp_sum(c);
        if (!lane) {
            float mean = a * (1.f/1024.f);
            float var  = c * (1.f/1024.f) - mean*mean;
            stats[0] = mean; stats[1] = rsqrtf(var + EPSL);
        }
    }
    __syncthreads();
    float mean = stats[0], rstd = stats[1];
#pragma unroll
    for (int i = 0; i < 4; i++) {
        int c = threadIdx.x + i*256;
        float v = (vals[i] - mean) * rstd * g[c] + b[c];
        out[base + c] = v;
        if (tout) tout[base + c] = tanhf(v);
    }
}

// -------- generic SGEMM, double-buffered: C = A[M,K] @ B[K,N] (+bias)(+res)
__global__ void __launch_bounds__(256) sgemm128_kernel(
    const float* __restrict__ A, const float* __restrict__ Bm,
    const float* __restrict__ bias, const float* __restrict__ res,
    float* __restrict__ C, int M, int Nc, int K)
{
    __shared__ float As[2][8][128];
    __shared__ float Bs[2][8][128];
    const int tid = threadIdx.x;
    const int bm = blockIdx.y * 128;
    const int bn = blockIdx.x * 128;
    const int arow = tid >> 1;
    const int acol = (tid & 1) * 4;
    const int brow = tid >> 5;
    const int bcol = (tid & 31) * 4;
    const int tr = (tid >> 4) * 8;
    const int tc = (tid & 15) * 8;
    const float* Ap = A + (size_t)(bm + arow) * K + acol;
    const float* Bp = Bm + (size_t)brow * Nc + bn + bcol;
    float acc[8][8];
#pragma unroll
    for (int i = 0; i < 8; i++)
#pragma unroll
        for (int j = 0; j < 8; j++) acc[i][j] = 0.f;

    // prologue: load k0=0 tile into buffer 0
    float4 av = *(const float4*)(Ap);
    float4 bv = *(const float4*)(Bp);
    As[0][acol+0][arow] = av.x; As[0][acol+1][arow] = av.y;
    As[0][acol+2][arow] = av.z; As[0][acol+3][arow] = av.w;
    *(float4*)(&Bs[0][brow][bcol]) = bv;
    __syncthreads();

    int p = 0;
    for (int k0 = 8; k0 <= K; k0 += 8) {
        const bool more = (k0 < K);
        if (more) {
            av = *(const float4*)(Ap + k0);
            bv = *(const float4*)(Bp + (size_t)k0 * Nc);
        }
#pragma unroll
        for (int k = 0; k < 8; k++) {
            float4 a0 = *(const float4*)(&As[p][k][tr]);
            float4 a1 = *(const float4*)(&As[p][k][tr+4]);
            float4 b0 = *(const float4*)(&Bs[p][k][tc]);
            float4 b1 = *(const float4*)(&Bs[p][k][tc+4]);
            float a[8]  = {a0.x,a0.y,a0.z,a0.w,a1.x,a1.y,a1.z,a1.w};
            float bb[8] = {b0.x,b0.y,b0.z,b0.w,b1.x,b1.y,b1.z,b1.w};
#pragma unroll
            for (int i = 0; i < 8; i++)
#pragma unroll
                for (int j = 0; j < 8; j++)
                    acc[i][j] = fmaf(a[i], bb[j], acc[i][j]);
        }
        if (more) {
            const int q = p ^ 1;
            As[q][acol+0][arow] = av.x; As[q][acol+1][arow] = av.y;
            As[q][acol+2][arow] = av.z; As[q][acol+3][arow] = av.w;
            *(float4*)(&Bs[q][brow][bcol]) = bv;
            __syncthreads();
            p = q;
        }
    }
#pragma unroll
    for (int i = 0; i < 8; i++) {
        size_t rowoff = (size_t)(bm + tr + i) * Nc + bn + tc;
#pragma unroll
        for (int jj = 0; jj < 8; jj += 4) {
            float4 v;
            v.x = acc[i][jj+0]; v.y = acc[i][jj+1];
            v.z = acc[i][jj+2]; v.w = acc[i][jj+3];
            if (bias) {
                v.x += bias[bn+tc+jj+0]; v.y += bias[bn+tc+jj+1];
                v.z += bias[bn+tc+jj+2]; v.w += bias[bn+tc+jj+3];
            }
            if (res) {
                float4 r = *(const float4*)(res + rowoff + jj);
                v.x += r.x; v.y += r.y; v.z += r.z; v.w += r.w;
            }
            *(float4*)(C + rowoff + jj) = v;
        }
    }
}

// ---------- prep: build Qcat=[Q/scale, lam*tanh(Q)J], Kcat=[K, tanh(K)] ----
__global__ void __launch_bounds__(256) prep_kernel(
    const float* __restrict__ Q, const float* __restrict__ K,
    const float* __restrict__ J, const float* __restrict__ lam_p,
    float* __restrict__ QC, float* __restrict__ KC)
{
    __shared__ float Js[64*64];
    __shared__ float tq[64*64];
    const int s0 = blockIdx.x * 64;
    const int z  = blockIdx.y;               // b*H + h
    const int b  = z >> 4, h = z & 15;
    const int tid = threadIdx.x;

    for (int idx = tid; idx < 4096; idx += 256)
        Js[idx] = J[h*4096 + idx];           // J[h][i][e]

    const float lam = lam_p[0];
    for (int idx = tid; idx < 4096; idx += 256) {
        int r = idx >> 6, i = idx & 63;
        size_t grow = (size_t)(b*Sq + s0 + r) * Dm + h*HDim + i;
        float qv = Q[grow];
        float kv = K[grow];
        tq[idx] = tanhf(qv);
        size_t crow = ((size_t)z*Sq + s0 + r) * 128;
        QC[crow + i] = qv * SCALE_INV;
        KC[crow + i] = kv;
        KC[crow + 64 + i] = tanhf(kv);
    }
    __syncthreads();

    const int d  = tid & 63;
    const int r0 = tid >> 6;
    for (int rr = 0; rr < 16; rr++) {
        int r = r0 + rr*4;
        float sum = 0.f;
#pragma unroll 8
        for (int i = 0; i < 64; i++)
            sum = fmaf(tq[r*64 + i], Js[i*64 + d], sum);
        QC[((size_t)z*Sq + s0 + r)*128 + 64 + d] = lam * sum;
    }
}

// ---------- scores: S_z = QC_z @ KC_z^T (M=N=1024, K=128), batched over z --
// double-buffered
__global__ void __launch_bounds__(256) scores_kernel(
    const float* __restrict__ QC, const float* __restrict__ KC, float* __restrict__ Sc)
{
    __shared__ float As[2][8][128];
    __shared__ float Bs[2][8][128];
    const int z = blockIdx.z;
    const float* A  = QC + (size_t)z * Sq * 128;
    const float* Bm = KC + (size_t)z * Sq * 128;
    float* C = Sc + (size_t)z * Sq * Sq;
    const int tid = threadIdx.x;
    const int bm = blockIdx.y * 128, bn = blockIdx.x * 128;
    const int arow = tid >> 1, acol = (tid & 1) * 4;
    const int tr = (tid >> 4) * 8, tc = (tid & 15) * 8;
    const float* Ap = A  + (size_t)(bm+arow)*128 + acol;
    const float* Bp = Bm + (size_t)(bn+arow)*128 + acol;
    float acc[8][8];
#pragma unroll
    for (int i = 0; i < 8; i++)
#pragma unroll
        for (int j = 0; j < 8; j++) acc[i][j] = 0.f;

    float4 av = *(const float4*)(Ap);
    float4 bv = *(const float4*)(Bp);
    As[0][acol+0][arow] = av.x; As[0][acol+1][arow] = av.y;
    As[0][acol+2][arow] = av.z; As[0][acol+3][arow] = av.w;
    Bs[0][acol+0][arow] = bv.x; Bs[0][acol+1][arow] = bv.y;
    Bs[0][acol+2][arow] = bv.z; Bs[0][acol+3][arow] = bv.w;
    __syncthreads();

    int p = 0;
    for (int k0 = 8; k0 <= 128; k0 += 8) {
        const bool more = (k0 < 128);
        if (more) {
            av = *(const float4*)(Ap + k0);
            bv = *(const float4*)(Bp + k0);
        }
#pragma unroll
        for (int k = 0; k < 8; k++) {
            float4 a0 = *(const float4*)(&As[p][k][tr]);
            float4 a1 = *(const float4*)(&As[p][k][tr+4]);
            float4 b0 = *(const float4*)(&Bs[p][k][tc]);
            float4 b1 = *(const float4*)(&Bs[p][k][tc+4]);
            float a[8]  = {a0.x,a0.y,a0.z,a0.w,a1.x,a1.y,a1.z,a1.w};
            float bb[8] = {b0.x,b0.y,b0.z,b0.w,b1.x,b1.y,b1.z,b1.w};
#pragma unroll
            for (int i = 0; i < 8; i++)
#pragma unroll
                for (int j = 0; j < 8; j++)
                    acc[i][j] = fmaf(a[i], bb[j], acc[i][j]);
        }
        if (more) {
            const int q = p ^ 1;
            As[q][acol+0][arow] = av.x; As[q][acol+1][arow] = av.y;
            As[q][acol+2][arow] = av.z; As[q][acol+3][arow] = av.w;
            Bs[q][acol+0][arow] = bv.x; Bs[q][acol+1][arow] = bv.y;
            Bs[q][acol+2][arow] = bv.z; Bs[q][acol+3][arow] = bv.w;
            __syncthreads();
            p = q;
        }
    }
#pragma unroll
    for (int i = 0; i < 8; i++) {
        size_t rowoff = (size_t)(bm + tr + i) * Sq + bn + tc;
#pragma unroll
        for (int jj = 0; jj < 8; jj += 4) {
            float4 v;
            v.x = acc[i][jj+0]; v.y = acc[i][jj+1];
            v.z = acc[i][jj+2]; v.w = acc[i][jj+3];
            *(float4*)(C + rowoff + jj) = v;
        }
    }
}

// ---------- softmax over rows of 1024 --------------------------------------
__global__ void __launch_bounds__(256) softmax_kernel(float* __restrict__ Sc)
{
    __shared__ float sh[32];
    __shared__ float bval;
    float* row = Sc + (size_t)blockIdx.x * Sq;
    const int tid = threadIdx.x;
    const int lane = tid & 31, w = tid >> 5;
    float v[4];
    float m = -1e30f;
#pragma unroll
    for (int i = 0; i < 4; i++) { v[i] = row[tid + i*256]; m = fmaxf(m, v[i]); }
    m = warp_max(m);
    if (!lane) sh[w] = m;
    __syncthreads();
    if (w == 0) {
        float a = (lane < 8) ? sh[lane] : -1e30f;
        a = warp_max(a);
        if (!lane) bval = a;
    }
    __syncthreads();
    m = bval;
    float s = 0.f;
#pragma unroll
    for (int i = 0; i < 4; i++) { v[i] = __expf(v[i] - m); s += v[i]; }
    s = warp_sum(s);
    __syncthreads();
    if (!lane) sh[w] = s;
    __syncthreads();
    if (w == 0) {
        float a = (lane < 8) ? sh[lane] : 0.f;
        a = warp_sum(a);
        if (!lane) bval = a;
    }
    __syncthreads();
    float inv = 1.f / bval;
#pragma unroll
    for (int i = 0; i < 4; i++) row[tid + i*256] = v[i] * inv;
}

// ---------- PV: attn_z = P_z[1024,1024] @ V_z[1024,64], batched ------------
// double-buffered
__global__ void __launch_bounds__(128) pv_kernel(
    const float* __restrict__ P, const float* __restrict__ V, float* __restrict__ O)
{
    __shared__ float As[2][8][128];
    __shared__ float Bs[2][8][64];
    const int z = blockIdx.z;
    const int b = z >> 4, h = z & 15;
    const float* A  = P + (size_t)z * Sq * Sq;
    const float* Bm = V + (size_t)b * Sq * Dm + h*HDim;
    float* C = O + (size_t)b * Sq * Dm + h*HDim;
    const int tid = threadIdx.x;
    const int bm = blockIdx.y * 128;
    const int brow = tid >> 4, bcol = (tid & 15) * 4;
    const int tr = (tid >> 3) * 8, tc = (tid & 7) * 8;
    const float* Ap = A + (size_t)(bm + tid)*Sq;
    const float* Bp = Bm + (size_t)brow*Dm + bcol;
    float acc[8][8];
#pragma unroll
    for (int i = 0; i < 8; i++)
#pragma unroll
        for (int j = 0; j < 8; j++) acc[i][j] = 0.f;

    // prologue
    float4 a0 = *(const float4*)(Ap);
    float4 a1 = *(const float4*)(Ap + 4);
    float4 bv = *(const float4*)(Bp);
    As[0][0][tid]=a0.x; As[0][1][tid]=a0.y; As[0][2][tid]=a0.z; As[0][3][tid]=a0.w;
    As[0][4][tid]=a1.x; As[0][5][tid]=a1.y; As[0][6][tid]=a1.z; As[0][7][tid]=a1.w;
    *(float4*)(&Bs[0][brow][bcol]) = bv;
    __syncthreads();

    int p = 0;
    for (int k0 = 8; k0 <= Sq; k0 += 8) {
        const bool more = (k0 < Sq);
        if (more) {
            a0 = *(const float4*)(Ap + k0);
            a1 = *(const float4*)(Ap + k0 + 4);
            bv = *(const float4*)(Bp + (size_t)k0 * Dm);
        }
#pragma unroll
        for (int k = 0; k < 8; k++) {
            float4 aa0 = *(const float4*)(&As[p][k][tr]);
            float4 aa1 = *(const float4*)(&As[p][k][tr+4]);
            float4 bb0 = *(const float4*)(&Bs[p][k][tc]);
            float4 bb1 = *(const float4*)(&Bs[p][k][tc+4]);
            float a[8]  = {aa0.x,aa0.y,aa0.z,aa0.w,aa1.x,aa1.y,aa1.z,aa1.w};
            float bb[8] = {bb0.x,bb0.y,bb0.z,bb0.w,bb1.x,bb1.y,bb1.z,bb1.w};
#pragma unroll
            for (int i = 0; i < 8; i++)
#pragma unroll
                for (int j = 0; j < 8; j++)
                    acc[i][j] = fmaf(a[i], bb[j], acc[i][j]);
        }
        if (more) {
            const int q = p ^ 1;
            As[q][0][tid]=a0.x; As[q][1][tid]=a0.y; As[q][2][tid]=a0.z; As[q][3][tid]=a0.w;
            As[q][4][tid]=a1.x; As[q][5][tid]=a1.y; As[q][6][tid]=a1.z; As[q][7][tid]=a1.w;
            *(float4*)(&Bs[q][brow][bcol]) = bv;
            __syncthreads();
            p = q;
        }
    }
#pragma unroll
    for (int i = 0; i < 8; i++) {
        size_t rowoff = (size_t)(bm + tr + i) * Dm + tc;
#pragma unroll
        for (int jj = 0; jj < 8; jj += 4) {
            float4 v;
            v.x = acc[i][jj+0]; v.y = acc[i][jj+1];
            v.z = acc[i][jj+2]; v.w = acc[i][jj+3];
            *(float4*)(C + rowoff + jj) = v;
        }
    }
}

// ---------- FFN layer-1 epilogue: h1 = gelu(LN(ht + 0.5*spJ*tanh(ht))) -----
__global__ void __launch_bounds__(256) ffn_post_kernel(
    const float* __restrict__ ht, const float* __restrict__ sj,
    const float* __restrict__ g, const float* __restrict__ be,
    float* __restrict__ h1, float* __restrict__ th1)
{
    __shared__ float buf[FFd];
    __shared__ float sh[64];
    __shared__ float stats[2];
    const size_t base = (size_t)blockIdx.x * FFd;
    float s = 0.f, s2 = 0.f;
    for (int c = threadIdx.x; c < FFd; c += 256) {
        float t = ht[base + c];
        float v = fmaf(0.5f * sj[base + c], tanhf(t), t);
        buf[c] = v; s += v; s2 += v*v;
    }
    s = warp_sum(s); s2 = warp_sum(s2);
    int lane = threadIdx.x & 31, w = threadIdx.x >> 5;
    if (!lane) { sh[w] = s; sh[32+w] = s2; }
    __syncthreads();
    if (w == 0) {
        float a = (lane < 8) ? sh[lane] : 0.f;
        float c = (lane < 8) ? sh[32+lane] : 0.f;
        a = warp_sum(a); c = warp_sum(c);
        if (!lane) {
            float mean = a * (1.f/FFd);
            float var  = c * (1.f/FFd) - mean*mean;
            stats[0] = mean; stats[1] = rsqrtf(var + EPSL);
        }
    }
    __syncthreads();
    float mean = stats[0], rstd = stats[1];
    for (int c = threadIdx.x; c < FFd; c += 256) {
        float nv = (buf[c] - mean) * rstd * g[c] + be[c];
        float gl = gelu_exact(nv);
        h1[base + c] = gl;
        th1[base + c] = tanhf(gl);
    }
}

// ---------- final: out = x2 + gelu(LN(ht2 + 0.5*spJ2*tanh(ht2))) -----------
__global__ void __launch_bounds__(256) final_kernel(
    const float* __restrict__ ht2, const float* __restrict__ sj2,
    const float* __restrict__ x2, const float* __restrict__ g,
    const float* __restrict__ be, float* __restrict__ out)
{
    __shared__ float buf[Dm];
    __shared__ float sh[64];
    __shared__ float stats[2];
    const size_t base = (size_t)blockIdx.x * Dm;
    float s = 0.f, s2 = 0.f;
#pragma unroll
    for (int i = 0; i < 4; i++) {
        int c = threadIdx.x + i*256;
        float t = ht2[base + c];
        float v = fmaf(0.5f * sj2[base + c], tanhf(t), t);
        buf[c] = v; s += v; s2 += v*v;
    }
    s = warp_sum(s); s2 = warp_sum(s2);
    int lane = threadIdx.x & 31, w = threadIdx.x >> 5;
    if (!lane) { sh[w] = s; sh[32+w] = s2; }
    __syncthreads();
    if (w == 0) {
        float a = (lane < 8) ? sh[lane] : 0.f;
        float c = (lane < 8) ? sh[32+lane] : 0.f;
        a = warp_sum(a); c = warp_sum(c);
        if (!lane) {
            float mean = a * (1.f/Dm);
            float var  = c * (1.f/Dm) - mean*mean;
            stats[0] = mean; stats[1] = rsqrtf(var + EPSL);
        }
    }
    __syncthreads();
    float mean = stats[0], rstd = stats[1];
#pragma unroll
    for (int i = 0; i < 4; i++) {
        int c = threadIdx.x + i*256;
        float nv = (buf[c] - mean) * rstd * g[c] + be[c];
        out[base + c] = x2[base + c] + gelu_exact(nv);
    }
}

// ------------------------- host orchestration ------------------------------
extern "C" void kernel_launch(void* const* d_in, const int* in_sizes, int n_in,
                              void* d_out, int out_size)
{
    const float* x    = (const float*)d_in[0];
    const float* wq   = (const float*)d_in[1];
    const float* bq   = (const float*)d_in[2];
    const float* wk   = (const float*)d_in[3];
    const float* bk   = (const float*)d_in[4];
    const float* wv   = (const float*)d_in[5];
    const float* bv   = (const float*)d_in[6];
    const float* wo   = (const float*)d_in[7];
    const float* bo   = (const float*)d_in[8];
    const float* Jat  = (const float*)d_in[9];
    const float* lamA = (const float*)d_in[10];
    const float* gA   = (const float*)d_in[11];
    const float* bA   = (const float*)d_in[12];
    const float* W1   = (const float*)d_in[13];
    const float* b1   = (const float*)d_in[14];
    const float* J1   = (const float*)d_in[15];
    const float* g1w  = (const float*)d_in[17];
    const float* be1  = (const float*)d_in[18];
    const float* W2   = (const float*)d_in[19];
    const float* b2   = (const float*)d_in[20];
    const float* J2   = (const float*)d_in[21];
    const float* g2w  = (const float*)d_in[23];
    const float* be2  = (const float*)d_in[24];
    const float* gF   = (const float*)d_in[25];
    const float* bF   = (const float*)d_in[26];
    float* out = (float*)d_out;

    float *p_xn, *p_Q, *p_K, *p_V, *p_QC, *p_KC, *p_sc, *p_attn, *p_x2;
    float *p_h0, *p_th0, *p_ht, *p_spJ, *p_h1, *p_th1, *p_ht2, *p_spJ2;
    cudaGetSymbolAddress((void**)&p_xn,   g_xn);
    cudaGetSymbolAddress((void**)&p_Q,    g_Q);
    cudaGetSymbolAddress((void**)&p_K,    g_K);
    cudaGetSymbolAddress((void**)&p_V,    g_V);
    cudaGetSymbolAddress((void**)&p_QC,   g_QC);
    cudaGetSymbolAddress((void**)&p_KC,   g_KC);
    cudaGetSymbolAddress((void**)&p_sc,   g_sc);
    cudaGetSymbolAddress((void**)&p_attn, g_attn);
    cudaGetSymbolAddress((void**)&p_x2,   g_x2);
    cudaGetSymbolAddress((void**)&p_h0,   g_h0);
    cudaGetSymbolAddress((void**)&p_th0,  g_th0);
    cudaGetSymbolAddress((void**)&p_ht,   g_ht);
    cudaGetSymbolAddress((void**)&p_spJ,  g_spJ);
    cudaGetSymbolAddress((void**)&p_h1,   g_h1);
    cudaGetSymbolAddress((void**)&p_th1,  g_th1);
    cudaGetSymbolAddress((void**)&p_ht2,  g_ht2);
    cudaGetSymbolAddress((void**)&p_spJ2, g_spJ2);

    // 1. pre-attention LN
    ln1024_kernel<<<NT, 256>>>(x, gA, bA, p_xn, nullptr);

    // 2. QKV projections
    dim3 gDD(Dm/128, NT/128);   // (8, 32)
    sgemm128_kernel<<<gDD, 256>>>(p_xn, wq, bq, nullptr, p_Q, NT, Dm, Dm);
    sgemm128_kernel<<<gDD, 256>>>(p_xn, wk, bk, nullptr, p_K, NT, Dm, Dm);
    sgemm128_kernel<<<gDD, 256>>>(p_xn, wv, bv, nullptr, p_V, NT, Dm, Dm);

    // 3. build Qcat/Kcat (folds the QBNN delta into head-dim-128 attention)
    prep_kernel<<<dim3(Sq/64, NH), 256>>>(p_Q, p_K, Jat, lamA, p_QC, p_KC);

    // 4. scores + softmax + PV
    scores_kernel<<<dim3(Sq/128, Sq/128, NH), 256>>>(p_QC, p_KC, p_sc);
    softmax_kernel<<<NH*Sq, 256>>>(p_sc);
    pv_kernel<<<dim3(1, Sq/128, NH), 128>>>(p_sc, p_V, p_attn);

    // 5. output projection + residual (x2 = x + attn@wo + bo)
    sgemm128_kernel<<<gDD, 256>>>(p_attn, wo, bo, x, p_x2, NT, Dm, Dm);

    // 6. FFN pre-norm (+ tanh copy for s_prev)
    ln1024_kernel<<<NT, 256>>>(p_x2, gF, bF, p_h0, p_th0);

    // 7. FFN layer 1 GEMMs
    dim3 gDF(FFd/128, NT/128);  // (32, 32)
    sgemm128_kernel<<<gDF, 256>>>(p_h0,  W1, b1, nullptr, p_ht,  NT, FFd, Dm);
    sgemm128_kernel<<<gDF, 256>>>(p_th0, J1, nullptr, nullptr, p_spJ, NT, FFd, Dm);
    ffn_post_kernel<<<NT, 256>>>(p_ht, p_spJ, g1w, be1, p_h1, p_th1);

    // 8. FFN layer 2 GEMMs
    sgemm128_kernel<<<gDD, 256>>>(p_h1,  W2, b2, nullptr, p_ht2,  NT, Dm, FFd);
    sgemm128_kernel<<<gDD, 256>>>(p_th1, J2, nullptr, nullptr, p_spJ2, NT, Dm, FFd);

    // 9. final epilogue: out = x2 + gelu(LN(ht2 + 0.5*spJ2*tanh(ht2)))
    final_kernel<<<NT, 256>>>(p_ht2, p_spJ2, p_x2, g2w, be2, out);
}

// round 6
// speedup vs baseline: 1.1633x; 1.1633x over previous
#include <cuda_runtime.h>
#include <math.h>

#define Bz 4
#define Sq 1024
#define Dm 1024
#define Hh 16
#define HDim 64
#define FFd 4096
#define NT (Bz*Sq)     // 4096 tokens
#define NH (Bz*Hh)     // 64 (b,h) pairs
#define EPSL 1e-5f
#define SCALE_INV 0.125f   // 1/sqrt(64)

// ------------------------- scratch (device globals; no mallocs allowed) ----
__device__ float g_xn  [NT*Dm];
__device__ float g_Q   [NT*Dm];
__device__ float g_K   [NT*Dm];
__device__ float g_V   [NT*Dm];
__device__ float g_QC  [NH*Sq*128];
__device__ float g_KC  [NH*Sq*128];
__device__ float g_sc  [67108864];      // [NH, Sq, Sq] = 256 MB
__device__ float g_attn[NT*Dm];
__device__ float g_x2  [NT*Dm];
__device__ float g_h0  [NT*Dm];
__device__ float g_th0 [NT*Dm];
__device__ float g_ht  [NT*FFd];
__device__ float g_spJ [NT*FFd];
__device__ float g_h1  [NT*FFd];
__device__ float g_th1 [NT*FFd];
__device__ float g_ht2 [NT*Dm];
__device__ float g_spJ2[NT*Dm];

// ------------------------- helpers ----------------------------------------
__device__ __forceinline__ float warp_sum(float v) {
#pragma unroll
    for (int o = 16; o > 0; o >>= 1) v += __shfl_xor_sync(0xffffffffu, v, o);
    return v;
}
__device__ __forceinline__ float warp_max(float v) {
#pragma unroll
    for (int o = 16; o > 0; o >>= 1) v = fmaxf(v, __shfl_xor_sync(0xffffffffu, v, o));
    return v;
}
__device__ __forceinline__ float gelu_exact(float x) {
    return 0.5f * x * (1.0f + erff(x * 0.70710678118654752f));
}

// ------------------------- layernorm over 1024 cols (+optional tanh copy) --
__global__ void __launch_bounds__(256) ln1024_kernel(
    const float* __restrict__ x, const float* __restrict__ g,
    const float* __restrict__ b, float* __restrict__ out, float* __restrict__ tout)
{
    __shared__ float sh[64];
    __shared__ float stats[2];
    const size_t base = (size_t)blockIdx.x * 1024;
    float vals[4];
    float s = 0.f, s2 = 0.f;
#pragma unroll
    for (int i = 0; i < 4; i++) {
        float v = x[base + threadIdx.x + i*256];
        vals[i] = v; s += v; s2 += v*v;
    }
    s = warp_sum(s); s2 = warp_sum(s2);
    int lane = threadIdx.x & 31, w = threadIdx.x >> 5;
    if (!lane) { sh[w] = s; sh[32+w] = s2; }
    __syncthreads();
    if (w == 0) {
        float a = (lane < 8) ? sh[lane] : 0.f;
        float c = (lane < 8) ? sh[32+lane] : 0.f;
        a = warp_sum(a); c = warp_sum(c);
        if (!lane) {
            float mean = a * (1.f/1024.f);
            float var  = c * (1.f/1024.f) - mean*mean;
            stats[0] = mean; stats[1] = rsqrtf(var + EPSL);
        }
    }
    __syncthreads();
    float mean = stats[0], rstd = stats[1];
#pragma unroll
    for (int i = 0; i < 4; i++) {
        int c = threadIdx.x + i*256;
        float v = (vals[i] - mean) * rstd * g[c] + b[c];
        out[base + c] = v;
        if (tout) tout[base + c] = tanhf(v);
    }
}

// -------- generic SGEMM, double-buffered, conflict-free fragments ----------
// C = A[M,K] @ B[K,N] (+bias)(+res); block tile 128x128, warp tile 64x32,
// thread tile 8x8 split into four 4x4 quadrants (rows +0/+32, cols +0/+16).
__global__ void __launch_bounds__(256) sgemm128_kernel(
    const float* __restrict__ A, const float* __restrict__ Bm,
    const float* __restrict__ bias, const float* __restrict__ res,
    float* __restrict__ C, int M, int Nc, int K)
{
    __shared__ float As[2][8][128];
    __shared__ float Bs[2][8][128];
    const int tid  = threadIdx.x;
    const int bm   = blockIdx.y * 128;
    const int bn   = blockIdx.x * 128;
    const int w    = tid >> 5;
    const int lane = tid & 31;
    const int wm   = (w >> 2) * 64;      // 2 warp-rows
    const int wn   = (w & 3) * 32;       // 4 warp-cols
    const int r4   = (lane >> 2) * 4;    // 8 values: 0..28
    const int c4   = (lane & 3) * 4;     // 4 values: 0..12
    const int arow = tid >> 1;
    const int acol = (tid & 1) * 4;
    const int brow = tid >> 5;
    const int bcol = (tid & 31) * 4;
    const float* Ap = A + (size_t)(bm + arow) * K + acol;
    const float* Bp = Bm + (size_t)brow * Nc + bn + bcol;
    float acc[8][8];
#pragma unroll
    for (int i = 0; i < 8; i++)
#pragma unroll
        for (int j = 0; j < 8; j++) acc[i][j] = 0.f;

    // prologue: load k0=0 tile into buffer 0
    float4 av = *(const float4*)(Ap);
    float4 bv = *(const float4*)(Bp);
    As[0][acol+0][arow] = av.x; As[0][acol+1][arow] = av.y;
    As[0][acol+2][arow] = av.z; As[0][acol+3][arow] = av.w;
    *(float4*)(&Bs[0][brow][bcol]) = bv;
    __syncthreads();

    int p = 0;
    for (int k0 = 8; k0 <= K; k0 += 8) {
        const bool more = (k0 < K);
        if (more) {
            av = *(const float4*)(Ap + k0);
            bv = *(const float4*)(Bp + (size_t)k0 * Nc);
        }
#pragma unroll
        for (int k = 0; k < 8; k++) {
            float4 a0 = *(const float4*)(&As[p][k][wm + r4]);
            float4 a1 = *(const float4*)(&As[p][k][wm + 32 + r4]);
            float4 b0 = *(const float4*)(&Bs[p][k][wn + c4]);
            float4 b1 = *(const float4*)(&Bs[p][k][wn + 16 + c4]);
            float a[8]  = {a0.x,a0.y,a0.z,a0.w,a1.x,a1.y,a1.z,a1.w};
            float bb[8] = {b0.x,b0.y,b0.z,b0.w,b1.x,b1.y,b1.z,b1.w};
#pragma unroll
            for (int i = 0; i < 8; i++)
#pragma unroll
                for (int j = 0; j < 8; j++)
                    acc[i][j] = fmaf(a[i], bb[j], acc[i][j]);
        }
        if (more) {
            const int q = p ^ 1;
            As[q][acol+0][arow] = av.x; As[q][acol+1][arow] = av.y;
            As[q][acol+2][arow] = av.z; As[q][acol+3][arow] = av.w;
            *(float4*)(&Bs[q][brow][bcol]) = bv;
            __syncthreads();
            p = q;
        }
    }
#pragma unroll
    for (int ih = 0; ih < 2; ih++)
#pragma unroll
    for (int i = 0; i < 4; i++) {
        const int row = bm + wm + ih*32 + r4 + i;
        size_t rowoff = (size_t)row * Nc;
#pragma unroll
        for (int jh = 0; jh < 2; jh++) {
            const int col = bn + wn + jh*16 + c4;
            float4 v;
            v.x = acc[ih*4+i][jh*4+0]; v.y = acc[ih*4+i][jh*4+1];
            v.z = acc[ih*4+i][jh*4+2]; v.w = acc[ih*4+i][jh*4+3];
            if (bias) {
                v.x += bias[col+0]; v.y += bias[col+1];
                v.z += bias[col+2]; v.w += bias[col+3];
            }
            if (res) {
                float4 rr = *(const float4*)(res + rowoff + col);
                v.x += rr.x; v.y += rr.y; v.z += rr.z; v.w += rr.w;
            }
            *(float4*)(C + rowoff + col) = v;
        }
    }
}

// ---------- prep: build Qcat=[Q/scale, lam*tanh(Q)J], Kcat=[K, tanh(K)] ----
__global__ void __launch_bounds__(256) prep_kernel(
    const float* __restrict__ Q, const float* __restrict__ K,
    const float* __restrict__ J, const float* __restrict__ lam_p,
    float* __restrict__ QC, float* __restrict__ KC)
{
    __shared__ float Js[64*64];
    __shared__ float tq[64*64];
    const int s0 = blockIdx.x * 64;
    const int z  = blockIdx.y;               // b*H + h
    const int b  = z >> 4, h = z & 15;
    const int tid = threadIdx.x;

    for (int idx = tid; idx < 4096; idx += 256)
        Js[idx] = J[h*4096 + idx];           // J[h][i][e]

    const float lam = lam_p[0];
    for (int idx = tid; idx < 4096; idx += 256) {
        int r = idx >> 6, i = idx & 63;
        size_t grow = (size_t)(b*Sq + s0 + r) * Dm + h*HDim + i;
        float qv = Q[grow];
        float kv = K[grow];
        tq[idx] = tanhf(qv);
        size_t crow = ((size_t)z*Sq + s0 + r) * 128;
        QC[crow + i] = qv * SCALE_INV;
        KC[crow + i] = kv;
        KC[crow + 64 + i] = tanhf(kv);
    }
    __syncthreads();

    const int d  = tid & 63;
    const int r0 = tid >> 6;
    for (int rr = 0; rr < 16; rr++) {
        int r = r0 + rr*4;
        float sum = 0.f;
#pragma unroll 8
        for (int i = 0; i < 64; i++)
            sum = fmaf(tq[r*64 + i], Js[i*64 + d], sum);
        QC[((size_t)z*Sq + s0 + r)*128 + 64 + d] = lam * sum;
    }
}

// ---------- scores: S_z = QC_z @ KC_z^T (M=N=1024, K=128), batched over z --
// double-buffered, conflict-free fragments
__global__ void __launch_bounds__(256) scores_kernel(
    const float* __restrict__ QC, const float* __restrict__ KC, float* __restrict__ Sc)
{
    __shared__ float As[2][8][128];
    __shared__ float Bs[2][8][128];
    const int z = blockIdx.z;
    const float* A  = QC + (size_t)z * Sq * 128;
    const float* Bm = KC + (size_t)z * Sq * 128;
    float* C = Sc + (size_t)z * Sq * Sq;
    const int tid  = threadIdx.x;
    const int bm   = blockIdx.y * 128, bn = blockIdx.x * 128;
    const int w    = tid >> 5;
    const int lane = tid & 31;
    const int wm   = (w >> 2) * 64;
    const int wn   = (w & 3) * 32;
    const int r4   = (lane >> 2) * 4;
    const int c4   = (lane & 3) * 4;
    const int arow = tid >> 1, acol = (tid & 1) * 4;
    const float* Ap = A  + (size_t)(bm+arow)*128 + acol;
    const float* Bp = Bm + (size_t)(bn+arow)*128 + acol;
    float acc[8][8];
#pragma unroll
    for (int i = 0; i < 8; i++)
#pragma unroll
        for (int j = 0; j < 8; j++) acc[i][j] = 0.f;

    float4 av = *(const float4*)(Ap);
    float4 bv = *(const float4*)(Bp);
    As[0][acol+0][arow] = av.x; As[0][acol+1][arow] = av.y;
    As[0][acol+2][arow] = av.z; As[0][acol+3][arow] = av.w;
    Bs[0][acol+0][arow] = bv.x; Bs[0][acol+1][arow] = bv.y;
    Bs[0][acol+2][arow] = bv.z; Bs[0][acol+3][arow] = bv.w;
    __syncthreads();

    int p = 0;
    for (int k0 = 8; k0 <= 128; k0 += 8) {
        const bool more = (k0 < 128);
        if (more) {
            av = *(const float4*)(Ap + k0);
            bv = *(const float4*)(Bp + k0);
        }
#pragma unroll
        for (int k = 0; k < 8; k++) {
            float4 a0 = *(const float4*)(&As[p][k][wm + r4]);
            float4 a1 = *(const float4*)(&As[p][k][wm + 32 + r4]);
            float4 b0 = *(const float4*)(&Bs[p][k][wn + c4]);
            float4 b1 = *(const float4*)(&Bs[p][k][wn + 16 + c4]);
            float a[8]  = {a0.x,a0.y,a0.z,a0.w,a1.x,a1.y,a1.z,a1.w};
            float bb[8] = {b0.x,b0.y,b0.z,b0.w,b1.x,b1.y,b1.z,b1.w};
#pragma unroll
            for (int i = 0; i < 8; i++)
#pragma unroll
                for (int j = 0; j < 8; j++)
                    acc[i][j] = fmaf(a[i], bb[j], acc[i][j]);
        }
        if (more) {
            const int q = p ^ 1;
            As[q][acol+0][arow] = av.x; As[q][acol+1][arow] = av.y;
            As[q][acol+2][arow] = av.z; As[q][acol+3][arow] = av.w;
            Bs[q][acol+0][arow] = bv.x; Bs[q][acol+1][arow] = bv.y;
            Bs[q][acol+2][arow] = bv.z; Bs[q][acol+3][arow] = bv.w;
            __syncthreads();
            p = q;
        }
    }
#pragma unroll
    for (int ih = 0; ih < 2; ih++)
#pragma unroll
    for (int i = 0; i < 4; i++) {
        const int row = bm + wm + ih*32 + r4 + i;
        size_t rowoff = (size_t)row * Sq;
#pragma unroll
        for (int jh = 0; jh < 2; jh++) {
            const int col = bn + wn + jh*16 + c4;
            float4 v;
            v.x = acc[ih*4+i][jh*4+0]; v.y = acc[ih*4+i][jh*4+1];
            v.z = acc[ih*4+i][jh*4+2]; v.w = acc[ih*4+i][jh*4+3];
            *(float4*)(C + rowoff + col) = v;
        }
    }
}

// ---------- softmax over rows of 1024 --------------------------------------
__global__ void __launch_bounds__(256) softmax_kernel(float* __restrict__ Sc)
{
    __shared__ float sh[32];
    __shared__ float bval;
    float* row = Sc + (size_t)blockIdx.x * Sq;
    const int tid = threadIdx.x;
    const int lane = tid & 31, w = tid >> 5;
    float v[4];
    float m = -1e30f;
#pragma unroll
    for (int i = 0; i < 4; i++) { v[i] = row[tid + i*256]; m = fmaxf(m, v[i]); }
    m = warp_max(m);
    if (!lane) sh[w] = m;
    __syncthreads();
    if (w == 0) {
        float a = (lane < 8) ? sh[lane] : -1e30f;
        a = warp_max(a);
        if (!lane) bval = a;
    }
    __syncthreads();
    m = bval;
    float s = 0.f;
#pragma unroll
    for (int i = 0; i < 4; i++) { v[i] = __expf(v[i] - m); s += v[i]; }
    s = warp_sum(s);
    __syncthreads();
    if (!lane) sh[w] = s;
    __syncthreads();
    if (w == 0) {
        float a = (lane < 8) ? sh[lane] : 0.f;
        a = warp_sum(a);
        if (!lane) bval = a;
    }
    __syncthreads();
    float inv = 1.f / bval;
#pragma unroll
    for (int i = 0; i < 4; i++) row[tid + i*256] = v[i] * inv;
}

// ---------- PV: attn_z = P_z[1024,1024] @ V_z[1024,64], batched ------------
// double-buffered, conflict-free fragments; block 128x64, warps 2x2
__global__ void __launch_bounds__(128) pv_kernel(
    const float* __restrict__ P, const float* __restrict__ V, float* __restrict__ O)
{
    __shared__ float As[2][8][128];
    __shared__ float Bs[2][8][64];
    const int z = blockIdx.z;
    const int b = z >> 4, h = z & 15;
    const float* A  = P + (size_t)z * Sq * Sq;
    const float* Bm = V + (size_t)b * Sq * Dm + h*HDim;
    float* C = O + (size_t)b * Sq * Dm + h*HDim;
    const int tid  = threadIdx.x;
    const int bm   = blockIdx.y * 128;
    const int w    = tid >> 5;
    const int lane = tid & 31;
    const int wm   = (w >> 1) * 64;      // 2 warp-rows
    const int wn   = (w & 1) * 32;       // 2 warp-cols
    const int r4   = (lane >> 2) * 4;
    const int c4   = (lane & 3) * 4;
    const int brow = tid >> 4, bcol = (tid & 15) * 4;
    const float* Ap = A + (size_t)(bm + tid)*Sq;
    const float* Bp = Bm + (size_t)brow*Dm + bcol;
    float acc[8][8];
#pragma unroll
    for (int i = 0; i < 8; i++)
#pragma unroll
        for (int j = 0; j < 8; j++) acc[i][j] = 0.f;

    // prologue
    float4 a0 = *(const float4*)(Ap);
    float4 a1 = *(const float4*)(Ap + 4);
    float4 bv = *(const float4*)(Bp);
    As[0][0][tid]=a0.x; As[0][1][tid]=a0.y; As[0][2][tid]=a0.z; As[0][3][tid]=a0.w;
    As[0][4][tid]=a1.x; As[0][5][tid]=a1.y; As[0][6][tid]=a1.z; As[0][7][tid]=a1.w;
    *(float4*)(&Bs[0][brow][bcol]) = bv;
    __syncthreads();

    int p = 0;
    for (int k0 = 8; k0 <= Sq; k0 += 8) {
        const bool more = (k0 < Sq);
        if (more) {
            a0 = *(const float4*)(Ap + k0);
            a1 = *(const float4*)(Ap + k0 + 4);
            bv = *(const float4*)(Bp + (size_t)k0 * Dm);
        }
#pragma unroll
        for (int k = 0; k < 8; k++) {
            float4 aa0 = *(const float4*)(&As[p][k][wm + r4]);
            float4 aa1 = *(const float4*)(&As[p][k][wm + 32 + r4]);
            float4 bb0 = *(const float4*)(&Bs[p][k][wn + c4]);
            float4 bb1 = *(const float4*)(&Bs[p][k][wn + 16 + c4]);
            float a[8]  = {aa0.x,aa0.y,aa0.z,aa0.w,aa1.x,aa1.y,aa1.z,aa1.w};
            float bb[8] = {bb0.x,bb0.y,bb0.z,bb0.w,bb1.x,bb1.y,bb1.z,bb1.w};
#pragma unroll
            for (int i = 0; i < 8; i++)
#pragma unroll
                for (int j = 0; j < 8; j++)
                    acc[i][j] = fmaf(a[i], bb[j], acc[i][j]);
        }
        if (more) {
            const int q = p ^ 1;
            As[q][0][tid]=a0.x; As[q][1][tid]=a0.y; As[q][2][tid]=a0.z; As[q][3][tid]=a0.w;
            As[q][4][tid]=a1.x; As[q][5][tid]=a1.y; As[q][6][tid]=a1.z; As[q][7][tid]=a1.w;
            *(float4*)(&Bs[q][brow][bcol]) = bv;
            __syncthreads();
            p = q;
        }
    }
#pragma unroll
    for (int ih = 0; ih < 2; ih++)
#pragma unroll
    for (int i = 0; i < 4; i++) {
        const int row = bm + wm + ih*32 + r4 + i;
        size_t rowoff = (size_t)row * Dm;
#pragma unroll
        for (int jh = 0; jh < 2; jh++) {
            const int col = wn + jh*16 + c4;
            float4 v;
            v.x = acc[ih*4+i][jh*4+0]; v.y = acc[ih*4+i][jh*4+1];
            v.z = acc[ih*4+i][jh*4+2]; v.w = acc[ih*4+i][jh*4+3];
            *(float4*)(C + rowoff + col) = v;
        }
    }
}

// ---------- FFN layer-1 epilogue: h1 = gelu(LN(ht + 0.5*spJ*tanh(ht))) -----
__global__ void __launch_bounds__(256) ffn_post_kernel(
    const float* __restrict__ ht, const float* __restrict__ sj,
    const float* __restrict__ g, const float* __restrict__ be,
    float* __restrict__ h1, float* __restrict__ th1)
{
    __shared__ float buf[FFd];
    __shared__ float sh[64];
    __shared__ float stats[2];
    const size_t base = (size_t)blockIdx.x * FFd;
    float s = 0.f, s2 = 0.f;
    for (int c = threadIdx.x; c < FFd; c += 256) {
        float t = ht[base + c];
        float v = fmaf(0.5f * sj[base + c], tanhf(t), t);
        buf[c] = v; s += v; s2 += v*v;
    }
    s = warp_sum(s); s2 = warp_sum(s2);
    int lane = threadIdx.x & 31, w = threadIdx.x >> 5;
    if (!lane) { sh[w] = s; sh[32+w] = s2; }
    __syncthreads();
    if (w == 0) {
        float a = (lane < 8) ? sh[lane] : 0.f;
        float c = (lane < 8) ? sh[32+lane] : 0.f;
        a = warp_sum(a); c = warp_sum(c);
        if (!lane) {
            float mean = a * (1.f/FFd);
            float var  = c * (1.f/FFd) - mean*mean;
            stats[0] = mean; stats[1] = rsqrtf(var + EPSL);
        }
    }
    __syncthreads();
    float mean = stats[0], rstd = stats[1];
    for (int c = threadIdx.x; c < FFd; c += 256) {
        float nv = (buf[c] - mean) * rstd * g[c] + be[c];
        float gl = gelu_exact(nv);
        h1[base + c] = gl;
        th1[base + c] = tanhf(gl);
    }
}

// ---------- final: out = x2 + gelu(LN(ht2 + 0.5*spJ2*tanh(ht2))) -----------
__global__ void __launch_bounds__(256) final_kernel(
    const float* __restrict__ ht2, const float* __restrict__ sj2,
    const float* __restrict__ x2, const float* __restrict__ g,
    const float* __restrict__ be, float* __restrict__ out)
{
    __shared__ float buf[Dm];
    __shared__ float sh[64];
    __shared__ float stats[2];
    const size_t base = (size_t)blockIdx.x * Dm;
    float s = 0.f, s2 = 0.f;
#pragma unroll
    for (int i = 0; i < 4; i++) {
        int c = threadIdx.x + i*256;
        float t = ht2[base + c];
        float v = fmaf(0.5f * sj2[base + c], tanhf(t), t);
        buf[c] = v; s += v; s2 += v*v;
    }
    s = warp_sum(s); s2 = warp_sum(s2);
    int lane = threadIdx.x & 31, w = threadIdx.x >> 5;
    if (!lane) { sh[w] = s; sh[32+w] = s2; }
    __syncthreads();
    if (w == 0) {
        float a = (lane < 8) ? sh[lane] : 0.f;
        float c = (lane < 8) ? sh[32+lane] : 0.f;
        a = warp_sum(a); c = warp_sum(c);
        if (!lane) {
            float mean = a * (1.f/Dm);
            float var  = c * (1.f/Dm) - mean*mean;
            stats[0] = mean; stats[1] = rsqrtf(var + EPSL);
        }
    }
    __syncthreads();
    float mean = stats[0], rstd = stats[1];
#pragma unroll
    for (int i = 0; i < 4; i++) {
        int c = threadIdx.x + i*256;
        float nv = (buf[c] - mean) * rstd * g[c] + be[c];
        out[base + c] = x2[base + c] + gelu_exact(nv);
    }
}

// ------------------------- host orchestration ------------------------------
extern "C" void kernel_launch(void* const* d_in, const int* in_sizes, int n_in,
                              void* d_out, int out_size)
{
    const float* x    = (const float*)d_in[0];
    const float* wq   = (const float*)d_in[1];
    const float* bq   = (const float*)d_in[2];
    const float* wk   = (const float*)d_in[3];
    const float* bk   = (const float*)d_in[4];
    const float* wv   = (const float*)d_in[5];
    const float* bv   = (const float*)d_in[6];
    const float* wo   = (const float*)d_in[7];
    const float* bo   = (const float*)d_in[8];
    const float* Jat  = (const float*)d_in[9];
    const float* lamA = (const float*)d_in[10];
    const float* gA   = (const float*)d_in[11];
    const float* bA   = (const float*)d_in[12];
    const float* W1   = (const float*)d_in[13];
    const float* b1   = (const float*)d_in[14];
    const float* J1   = (const float*)d_in[15];
    const float* g1w  = (const float*)d_in[17];
    const float* be1  = (const float*)d_in[18];
    const float* W2   = (const float*)d_in[19];
    const float* b2   = (const float*)d_in[20];
    const float* J2   = (const float*)d_in[21];
    const float* g2w  = (const float*)d_in[23];
    const float* be2  = (const float*)d_in[24];
    const float* gF   = (const float*)d_in[25];
    const float* bF   = (const float*)d_in[26];
    float* out = (float*)d_out;

    float *p_xn, *p_Q, *p_K, *p_V, *p_QC, *p_KC, *p_sc, *p_attn, *p_x2;
    float *p_h0, *p_th0, *p_ht, *p_spJ, *p_h1, *p_th1, *p_ht2, *p_spJ2;
    cudaGetSymbolAddress((void**)&p_xn,   g_xn);
    cudaGetSymbolAddress((void**)&p_Q,    g_Q);
    cudaGetSymbolAddress((void**)&p_K,    g_K);
    cudaGetSymbolAddress((void**)&p_V,    g_V);
    cudaGetSymbolAddress((void**)&p_QC,   g_QC);
    cudaGetSymbolAddress((void**)&p_KC,   g_KC);
    cudaGetSymbolAddress((void**)&p_sc,   g_sc);
    cudaGetSymbolAddress((void**)&p_attn, g_attn);
    cudaGetSymbolAddress((void**)&p_x2,   g_x2);
    cudaGetSymbolAddress((void**)&p_h0,   g_h0);
    cudaGetSymbolAddress((void**)&p_th0,  g_th0);
    cudaGetSymbolAddress((void**)&p_ht,   g_ht);
    cudaGetSymbolAddress((void**)&p_spJ,  g_spJ);
    cudaGetSymbolAddress((void**)&p_h1,   g_h1);
    cudaGetSymbolAddress((void**)&p_th1,  g_th1);
    cudaGetSymbolAddress((void**)&p_ht2,  g_ht2);
    cudaGetSymbolAddress((void**)&p_spJ2, g_spJ2);

    // 1. pre-attention LN
    ln1024_kernel<<<NT, 256>>>(x, gA, bA, p_xn, nullptr);

    // 2. QKV projections
    dim3 gDD(Dm/128, NT/128);   // (8, 32)
    sgemm128_kernel<<<gDD, 256>>>(p_xn, wq, bq, nullptr, p_Q, NT, Dm, Dm);
    sgemm128_kernel<<<gDD, 256>>>(p_xn, wk, bk, nullptr, p_K, NT, Dm, Dm);
    sgemm128_kernel<<<gDD, 256>>>(p_xn, wv, bv, nullptr, p_V, NT, Dm, Dm);

    // 3. build Qcat/Kcat (folds the QBNN delta into head-dim-128 attention)
    prep_kernel<<<dim3(Sq/64, NH), 256>>>(p_Q, p_K, Jat, lamA, p_QC, p_KC);

    // 4. scores + softmax + PV
    scores_kernel<<<dim3(Sq/128, Sq/128, NH), 256>>>(p_QC, p_KC, p_sc);
    softmax_kernel<<<NH*Sq, 256>>>(p_sc);
    pv_kernel<<<dim3(1, Sq/128, NH), 128>>>(p_sc, p_V, p_attn);

    // 5. output projection + residual (x2 = x + attn@wo + bo)
    sgemm128_kernel<<<gDD, 256>>>(p_attn, wo, bo, x, p_x2, NT, Dm, Dm);

    // 6. FFN pre-norm (+ tanh copy for s_prev)
    ln1024_kernel<<<NT, 256>>>(p_x2, gF, bF, p_h0, p_th0);

    // 7. FFN layer 1 GEMMs
    dim3 gDF(FFd/128, NT/128);  // (32, 32)
    sgemm128_kernel<<<gDF, 256>>>(p_h0,  W1, b1, nullptr, p_ht,  NT, FFd, Dm);
    sgemm128_kernel<<<gDF, 256>>>(p_th0, J1, nullptr, nullptr, p_spJ, NT, FFd, Dm);
    ffn_post_kernel<<<NT, 256>>>(p_ht, p_spJ, g1w, be1, p_h1, p_th1);

    // 8. FFN layer 2 GEMMs
    sgemm128_kernel<<<gDD, 256>>>(p_h1,  W2, b2, nullptr, p_ht2,  NT, Dm, FFd);
    sgemm128_kernel<<<gDD, 256>>>(p_th1, J2, nullptr, nullptr, p_spJ2, NT, Dm, FFd);

    // 9. final epilogue: out = x2 + gelu(LN(ht2 + 0.5*spJ2*tanh(ht2)))
    final_kernel<<<NT, 256>>>(p_ht2, p_spJ2, p_x2, g2w, be2, out);
}